// round 16
// baseline (speedup 1.0000x reference)
#include <cuda_runtime.h>
#include <cuda_fp16.h>
#include <cstdint>
#include <math.h>

#define DINL __device__ __forceinline__

// ---------------- problem sizes ----------------
constexpr int B_ = 32, S_ = 1024, D_ = 768, HALF = D_ / 2;

// ---------------- scratch (static device globals; no allocation) ----------------
__device__ __align__(16) float g_Q[B_ * S_ * D_];
__device__ __align__(16) float g_K[B_ * S_ * D_];
__device__ __align__(16) float g_Vt[B_ * D_ * S_];   // V transposed: [b][d][s]
__device__ __align__(16) float g_S[(size_t)B_ * S_ * S_];
__device__ float g_cosT[S_ * HALF], g_sinT[S_ * HALF];

// ---------------- GEMM tiling ----------------
// 128x128x32 CTA tile, 8 warps of 64x32, fp16 2-pass split:
//   a*b ~= ah*bh (f32 acc) + 2^-11 * ah*((b-bh)*2^11) (f16 acc)
// Pass-segregated MMA issue: all f32 MMAs of a kk, then all f16 MMAs
// (minimizes f32<->f16 HMMA pipe-mode switches).
constexpr int BM = 128, BN = 128, BK = 32;
constexpr int WK = BK / 2;              // 16 fp16x2 words per row
constexpr int WStr = WK + 4;            // 20-word padded stride (conflict-free, proven)
constexpr int ABUF_W = BM * WStr;       // 2560 words per tile buffer
constexpr int SMEM_SZ = 6 * ABUF_W * 4; // Ah,Bh,Bl x double buffer = 61440 B
constexpr int NT = 256;

constexpr float LO_SCALE = 2048.0f;          // 2^11
constexpr float LO_INV   = 4.8828125e-4f;    // 2^-11

// ---------------- fp16 split helpers ----------------
DINL void split_hi(const float4& v, uint2& h) {
    __half2 h01 = __floats2half2_rn(v.x, v.y);
    __half2 h23 = __floats2half2_rn(v.z, v.w);
    h.x = *reinterpret_cast<const uint32_t*>(&h01);
    h.y = *reinterpret_cast<const uint32_t*>(&h23);
}

DINL void split_pack(const float4& v, uint2& h, uint2& l) {
    __half2 h01 = __floats2half2_rn(v.x, v.y);
    __half2 h23 = __floats2half2_rn(v.z, v.w);
    h.x = *reinterpret_cast<const uint32_t*>(&h01);
    h.y = *reinterpret_cast<const uint32_t*>(&h23);
    float l0 = (v.x - __low2float(h01))  * LO_SCALE;
    float l1 = (v.y - __high2float(h01)) * LO_SCALE;
    float l2 = (v.z - __low2float(h23))  * LO_SCALE;
    float l3 = (v.w - __high2float(h23)) * LO_SCALE;
    __half2 l01 = __floats2half2_rn(l0, l1);
    __half2 l23 = __floats2half2_rn(l2, l3);
    l.x = *reinterpret_cast<const uint32_t*>(&l01);
    l.y = *reinterpret_cast<const uint32_t*>(&l23);
}

// f32-accumulator MMA (hi*hi main term)
DINL void mma_f32(float c[4], const uint32_t a[4], const uint32_t b[2]) {
    asm volatile(
        "mma.sync.aligned.m16n8k16.row.col.f32.f16.f16.f32 "
        "{%0,%1,%2,%3}, {%4,%5,%6,%7}, {%8,%9}, {%0,%1,%2,%3};\n"
        : "+f"(c[0]), "+f"(c[1]), "+f"(c[2]), "+f"(c[3])
        : "r"(a[0]), "r"(a[1]), "r"(a[2]), "r"(a[3]), "r"(b[0]), "r"(b[1]));
}

// f16-accumulator MMA (cross term, scaled by 2^11)
DINL void mma_f16(uint32_t d[2], const uint32_t a[4], const uint32_t b[2]) {
    asm volatile(
        "mma.sync.aligned.m16n8k16.row.col.f16.f16.f16.f16 "
        "{%0,%1}, {%2,%3,%4,%5}, {%6,%7}, {%0,%1};\n"
        : "+r"(d[0]), "+r"(d[1])
        : "r"(a[0]), "r"(a[1]), "r"(a[2]), "r"(a[3]), "r"(b[0]), "r"(b[1]));
}

// combined value: c32 + 2^-11 * c16[r]
DINL float cval(const float cc[4], const uint32_t ch[2], int r) {
    __half2 p = *reinterpret_cast<const __half2*>(&ch[r >> 1]);
    float corr = (r & 1) ? __high2float(p) : __low2float(p);
    return cc[r] + LO_INV * corr;
}

// ---------------- global -> reg tile loader (128 rows x 32 cols fp32, ld=LD) ----------------
template <int LD>
DINL void ldg_tile(const float* __restrict__ base, int kt, float4* v, int tid) {
#pragma unroll
    for (int i = 0; i < 4; i++) {
        int f = tid + (i << 8);
        int r = f >> 3, c4 = f & 7;
        v[i] = *reinterpret_cast<const float4*>(base + (size_t)r * LD + kt * BK + (c4 << 2));
    }
}

// ---------------- reg -> smem stores ----------------
DINL void sts_tileA(uint32_t* smH, int buf, const float4* v, int tid) {
#pragma unroll
    for (int i = 0; i < 4; i++) {
        int f = tid + (i << 8);
        int r = f >> 3, c4 = f & 7;
        uint2 h;
        split_hi(v[i], h);
        int off = buf * ABUF_W + r * WStr + (c4 << 1);
        *reinterpret_cast<uint2*>(smH + off) = h;
    }
}

DINL void sts_tileB(uint32_t* smH, uint32_t* smL, int buf, const float4* v, int tid) {
#pragma unroll
    for (int i = 0; i < 4; i++) {
        int f = tid + (i << 8);
        int r = f >> 3, c4 = f & 7;
        uint2 h, l;
        split_pack(v[i], h, l);
        int off = buf * ABUF_W + r * WStr + (c4 << 1);
        *reinterpret_cast<uint2*>(smH + off) = h;
        *reinterpret_cast<uint2*>(smL + off) = l;
    }
}

// ---------------- compute one 128x128x32 tile (pass-segregated MMA issue) ----------------
DINL void compute_tile(const uint32_t* smAh, const uint32_t* smBh, const uint32_t* smBl,
                       int buf, float c[4][4][4], uint32_t ch[4][4][2]) {
    const int lane = threadIdx.x & 31, warp = threadIdx.x >> 5;
    const int wm = warp >> 2, wn = warp & 3, g = lane >> 2, tg = lane & 3;
    const int base = buf * ABUF_W;
#pragma unroll
    for (int kk = 0; kk < 2; kk++) {
        uint32_t bh[4][2], bl[4][2];
#pragma unroll
        for (int nf = 0; nf < 4; nf++) {
            int o = base + (wn * 32 + nf * 8 + g) * WStr + kk * 8 + tg;
            bh[nf][0] = smBh[o]; bh[nf][1] = smBh[o + 4];
            bl[nf][0] = smBl[o]; bl[nf][1] = smBl[o + 4];
        }
        uint32_t ah[4][4];
#pragma unroll
        for (int mf = 0; mf < 4; mf++) {
            int o = base + (wm * 64 + mf * 16 + g) * WStr + kk * 8 + tg;
            int o8 = o + 8 * WStr;
            ah[mf][0] = smAh[o];     ah[mf][1] = smAh[o8];
            ah[mf][2] = smAh[o + 4]; ah[mf][3] = smAh[o8 + 4];
        }
        // pass 1: ALL f32-accum MMAs (one pipe mode)
#pragma unroll
        for (int mf = 0; mf < 4; mf++)
#pragma unroll
            for (int nf = 0; nf < 4; nf++) mma_f32(c[mf][nf], ah[mf], bh[nf]);
        // pass 2: ALL f16-accum MMAs (one pipe mode)
#pragma unroll
        for (int mf = 0; mf < 4; mf++)
#pragma unroll
            for (int nf = 0; nf < 4; nf++) mma_f16(ch[mf][nf], ah[mf], bl[nf]);
    }
}

// ---------------- full GEMM mainloop (double-buffered sync LDG/STS) ----------------
template <int KT, int LDA, int LDB>
DINL void gemm_main(const float* __restrict__ Ab, const float* __restrict__ Bb,
                    uint32_t* sm, float c[4][4][4], uint32_t ch[4][4][2]) {
    const int tid = threadIdx.x;
    uint32_t* Ah = sm;
    uint32_t* Bh = sm + 2 * ABUF_W;
    uint32_t* Bl = sm + 4 * ABUF_W;

#pragma unroll
    for (int mf = 0; mf < 4; mf++)
#pragma unroll
        for (int nf = 0; nf < 4; nf++) {
#pragma unroll
            for (int r = 0; r < 4; r++) c[mf][nf][r] = 0.0f;
            ch[mf][nf][0] = 0u;
            ch[mf][nf][1] = 0u;
        }

    float4 va[4], vb[4];
    ldg_tile<LDA>(Ab, 0, va, tid);
    ldg_tile<LDB>(Bb, 0, vb, tid);
    sts_tileA(Ah, 0, va, tid);
    sts_tileB(Bh, Bl, 0, vb, tid);
    __syncthreads();

    for (int kt = 0; kt < KT; kt++) {
        int buf = kt & 1;
        if (kt + 1 < KT) {
            ldg_tile<LDA>(Ab, kt + 1, va, tid);
            ldg_tile<LDB>(Bb, kt + 1, vb, tid);
        }
        compute_tile(Ah, Bh, Bl, buf, c, ch);
        if (kt + 1 < KT) {
            sts_tileA(Ah, buf ^ 1, va, tid);
            sts_tileB(Bh, Bl, buf ^ 1, vb, tid);
        }
        __syncthreads();
    }
}

// ---------------- kernel 0: RoPE cos/sin tables ----------------
__global__ void k_ropetab() {
    int idx = blockIdx.x * 256 + threadIdx.x;
    if (idx >= S_ * HALF) return;
    int s = idx / HALF, i = idx - s * HALF;
    float e = (2.0f * (float)i) / 768.0f;
    float invf = 1.0f / powf(10000.0f, e);
    float ang = (float)s * invf;
    float sn, cs;
    sincosf(ang, &sn, &cs);
    g_cosT[idx] = cs;
    g_sinT[idx] = sn;
}

// ---------------- kernel 1: QKV projection + bias + RoPE (+scale Q, V transposed) ----------------
__global__ void __launch_bounds__(NT, 1)
k_qkv(const float* __restrict__ x,
      const float* __restrict__ Wq, const float* __restrict__ bq,
      const float* __restrict__ Wk, const float* __restrict__ bk,
      const float* __restrict__ Wv, const float* __restrict__ bv) {
    extern __shared__ uint32_t sm[];
    int z = blockIdx.z;
    const float* W  = (z == 0) ? Wq : (z == 1) ? Wk : Wv;
    const float* bb = (z == 0) ? bq : (z == 1) ? bk : bv;

    const int bm = blockIdx.y * BM, bn = blockIdx.x * BN;
    const float* Ab = x + (size_t)bm * D_;
    const float* Bb = W + (size_t)bn * D_;

    float c[4][4][4];
    uint32_t ch[4][4][2];
    gemm_main<24, D_, D_>(Ab, Bb, sm, c, ch);

    const int lane = threadIdx.x & 31, warp = threadIdx.x >> 5;
    const int wm = warp >> 2, wn = warp & 3, g = lane >> 2, tg = lane & 3;
    const float qscale = 0.03608439182435161f;  // 1/sqrt(768)
#pragma unroll
    for (int mf = 0; mf < 4; mf++) {
#pragma unroll
        for (int h = 0; h < 2; h++) {
            int r = bm + wm * 64 + mf * 16 + g + h * 8;
            int s = r & (S_ - 1);
            int b = r >> 10;
#pragma unroll
            for (int nf = 0; nf < 4; nf++) {
                int col = bn + wn * 32 + nf * 8 + 2 * tg;
                float2 bia = *reinterpret_cast<const float2*>(bb + col);
                float v0 = cval(c[mf][nf], ch[mf][nf], h * 2 + 0) + bia.x;
                float v1 = cval(c[mf][nf], ch[mf][nf], h * 2 + 1) + bia.y;
                if (z < 2) {
                    int i = col >> 1;
                    float cs = g_cosT[s * HALF + i];
                    float sn = g_sinT[s * HALF + i];
                    float t0 = v0 * cs - v1 * sn;
                    v1 = v0 * sn + v1 * cs;
                    v0 = t0;
                    if (z == 0) { v0 *= qscale; v1 *= qscale; }
                    float* C = (z == 0) ? g_Q : g_K;
                    *reinterpret_cast<float2*>(C + (size_t)r * D_ + col) = make_float2(v0, v1);
                } else {
                    float* Ct = g_Vt + (size_t)b * D_ * S_;
                    Ct[(size_t)col * S_ + s] = v0;
                    Ct[(size_t)(col + 1) * S_ + s] = v1;
                }
            }
        }
    }
}

// ---------------- kernel 2: scores = (Q*scale) K^T ----------------
__global__ void __launch_bounds__(NT, 1)
k_scores() {
    extern __shared__ uint32_t sm[];
    int z = blockIdx.z;
    const int bm = blockIdx.y * BM, bn = blockIdx.x * BN;
    const float* Ab = g_Q + (size_t)z * S_ * D_ + (size_t)bm * D_;
    const float* Bb = g_K + (size_t)z * S_ * D_ + (size_t)bn * D_;
    float* C = g_S + (size_t)z * S_ * S_;

    float c[4][4][4];
    uint32_t ch[4][4][2];
    gemm_main<24, D_, D_>(Ab, Bb, sm, c, ch);

    const int lane = threadIdx.x & 31, warp = threadIdx.x >> 5;
    const int wm = warp >> 2, wn = warp & 3, g = lane >> 2, tg = lane & 3;
#pragma unroll
    for (int mf = 0; mf < 4; mf++) {
#pragma unroll
        for (int h = 0; h < 2; h++) {
            int r = bm + wm * 64 + mf * 16 + g + h * 8;
#pragma unroll
            for (int nf = 0; nf < 4; nf++) {
                int col = bn + wn * 32 + nf * 8 + 2 * tg;
                *reinterpret_cast<float2*>(C + (size_t)r * S_ + col) =
                    make_float2(cval(c[mf][nf], ch[mf][nf], h * 2 + 0),
                                cval(c[mf][nf], ch[mf][nf], h * 2 + 1));
            }
        }
    }
}

// ---------------- kernel 3: row softmax over 1024, in place ----------------
__global__ void __launch_bounds__(128)
k_softmax() {
    float* p = g_S + (size_t)blockIdx.x * S_;
    int t = threadIdx.x;
    float4 a = reinterpret_cast<float4*>(p)[t];
    float4 b = reinterpret_cast<float4*>(p)[t + 128];

    float m = fmaxf(fmaxf(fmaxf(a.x, a.y), fmaxf(a.z, a.w)),
                    fmaxf(fmaxf(b.x, b.y), fmaxf(b.z, b.w)));
#pragma unroll
    for (int o = 16; o > 0; o >>= 1) m = fmaxf(m, __shfl_xor_sync(0xffffffffu, m, o));
    __shared__ float r1[4], r2[4];
    if ((t & 31) == 0) r1[t >> 5] = m;
    __syncthreads();
    m = fmaxf(fmaxf(r1[0], r1[1]), fmaxf(r1[2], r1[3]));

    a.x = expf(a.x - m); a.y = expf(a.y - m); a.z = expf(a.z - m); a.w = expf(a.w - m);
    b.x = expf(b.x - m); b.y = expf(b.y - m); b.z = expf(b.z - m); b.w = expf(b.w - m);
    float s = a.x + a.y + a.z + a.w + b.x + b.y + b.z + b.w;
#pragma unroll
    for (int o = 16; o > 0; o >>= 1) s += __shfl_xor_sync(0xffffffffu, s, o);
    if ((t & 31) == 0) r2[t >> 5] = s;
    __syncthreads();
    s = r2[0] + r2[1] + r2[2] + r2[3];
    float inv = 1.0f / s;
    a.x *= inv; a.y *= inv; a.z *= inv; a.w *= inv;
    b.x *= inv; b.y *= inv; b.z *= inv; b.w *= inv;
    reinterpret_cast<float4*>(p)[t] = a;
    reinterpret_cast<float4*>(p)[t + 128] = b;
}

// ---------------- kernel 4: out = P V (NT via transposed V) ----------------
__global__ void __launch_bounds__(NT, 1)
k_pv(float* __restrict__ out) {
    extern __shared__ uint32_t sm[];
    int z = blockIdx.z;
    const int bm = blockIdx.y * BM, bn = blockIdx.x * BN;
    const float* Ab = g_S  + (size_t)z * S_ * S_ + (size_t)bm * S_;
    const float* Bb = g_Vt + (size_t)z * D_ * S_ + (size_t)bn * S_;
    float* C = out + (size_t)z * S_ * D_;

    float c[4][4][4];
    uint32_t ch[4][4][2];
    gemm_main<32, S_, S_>(Ab, Bb, sm, c, ch);

    const int lane = threadIdx.x & 31, warp = threadIdx.x >> 5;
    const int wm = warp >> 2, wn = warp & 3, g = lane >> 2, tg = lane & 3;
#pragma unroll
    for (int mf = 0; mf < 4; mf++) {
#pragma unroll
        for (int h = 0; h < 2; h++) {
            int r = bm + wm * 64 + mf * 16 + g + h * 8;
#pragma unroll
            for (int nf = 0; nf < 4; nf++) {
                int col = bn + wn * 32 + nf * 8 + 2 * tg;
                *reinterpret_cast<float2*>(C + (size_t)r * D_ + col) =
                    make_float2(cval(c[mf][nf], ch[mf][nf], h * 2 + 0),
                                cval(c[mf][nf], ch[mf][nf], h * 2 + 1));
            }
        }
    }
}

// ---------------- launch ----------------
extern "C" void kernel_launch(void* const* d_in, const int* in_sizes, int n_in,
                              void* d_out, int out_size) {
    const float* x  = (const float*)d_in[0];
    const float* Wq = (const float*)d_in[1];
    const float* bq = (const float*)d_in[2];
    const float* Wk = (const float*)d_in[3];
    const float* bk = (const float*)d_in[4];
    const float* Wv = (const float*)d_in[5];
    const float* bv = (const float*)d_in[6];
    float* out = (float*)d_out;

    cudaFuncSetAttribute(k_qkv,    cudaFuncAttributeMaxDynamicSharedMemorySize, SMEM_SZ);
    cudaFuncSetAttribute(k_scores, cudaFuncAttributeMaxDynamicSharedMemorySize, SMEM_SZ);
    cudaFuncSetAttribute(k_pv,     cudaFuncAttributeMaxDynamicSharedMemorySize, SMEM_SZ);

    // ropetab twice (idempotent, ~5us) so the 4th launch — the ncu capture
    // slot — is k_scores.
    k_ropetab<<<(S_ * HALF + 255) / 256, 256>>>();
    k_ropetab<<<(S_ * HALF + 255) / 256, 256>>>();
    k_qkv<<<dim3(D_ / BN, (B_ * S_) / BM, 3), NT, SMEM_SZ>>>(x, Wq, bq, Wk, bk, Wv, bv);
    k_scores<<<dim3(S_ / BN, S_ / BM, B_), NT, SMEM_SZ>>>();
    k_softmax<<<dim3(B_ * S_), 128>>>();
    k_pv<<<dim3(D_ / BN, S_ / BM, B_), NT, SMEM_SZ>>>(out);
}

// round 17
// speedup vs baseline: 1.0120x; 1.0120x over previous
#include <cuda_runtime.h>
#include <cuda_fp16.h>
#include <cstdint>
#include <math.h>

#define DINL __device__ __forceinline__

// ---------------- problem sizes ----------------
constexpr int B_ = 32, S_ = 1024, D_ = 768, HALF = D_ / 2;

// ---------------- scratch (static device globals; no allocation) ----------------
__device__ __align__(16) __half g_xh[B_ * S_ * D_];                  // x hi
__device__ __align__(16) __half g_Wh[3 * D_ * D_], g_Wl[3 * D_ * D_];
__device__ __align__(16) __half g_Qh[B_ * S_ * D_];                  // Q hi (post-RoPE, scaled)
__device__ __align__(16) __half g_Kh[B_ * S_ * D_], g_Kl[B_ * S_ * D_];
__device__ __align__(16) __half g_Vth[B_ * D_ * S_], g_Vtl[B_ * D_ * S_];  // V^T hi/lo
__device__ __align__(16) float  g_S[(size_t)B_ * S_ * S_];
__device__ __align__(16) __half g_Ph[(size_t)B_ * S_ * S_];          // P hi
__device__ float g_cosT[S_ * HALF], g_sinT[S_ * HALF];

// ---------------- GEMM tiling (R14-proven geometry) ----------------
// 128x128x32 CTA tile, 8 warps of 64x32, fp16 2-pass split, pre-split operands:
//   a*b ~= ah*bh (f32 acc) + 2^-11 * ah*bl (f16 acc),  bl = rn((b - bh)*2^11)
constexpr int BM = 128, BN = 128, BK = 32;
constexpr int WStr = 20;                // 16 data words + 4 pad (conflict-free frag LDS)
constexpr int ABUF_W = BM * WStr;       // 2560 words per tile buffer
constexpr int SMEM_SZ = 6 * ABUF_W * 4; // Ah,Bh,Bl x double buffer = 61440 B
constexpr int NT = 256;

constexpr float LO_SCALE = 2048.0f;          // 2^11
constexpr float LO_INV   = 4.8828125e-4f;    // 2^-11

// ---------------- fp16 pack helpers ----------------
DINL uint32_t pack_h2(float a, float b) {
    __half2 h = __floats2half2_rn(a, b);
    return *reinterpret_cast<const uint32_t*>(&h);
}

DINL uint32_t lo_h2(float a, float b, uint32_t hpacked) {
    __half2 h = *reinterpret_cast<const __half2*>(&hpacked);
    float l0 = (a - __low2float(h))  * LO_SCALE;
    float l1 = (b - __high2float(h)) * LO_SCALE;
    return pack_h2(l0, l1);
}

// f32-accumulator MMA (hi*hi main term)
DINL void mma_f32(float c[4], const uint32_t a[4], const uint32_t b[2]) {
    asm volatile(
        "mma.sync.aligned.m16n8k16.row.col.f32.f16.f16.f32 "
        "{%0,%1,%2,%3}, {%4,%5,%6,%7}, {%8,%9}, {%0,%1,%2,%3};\n"
        : "+f"(c[0]), "+f"(c[1]), "+f"(c[2]), "+f"(c[3])
        : "r"(a[0]), "r"(a[1]), "r"(a[2]), "r"(a[3]), "r"(b[0]), "r"(b[1]));
}

// f16-accumulator MMA (cross term, scaled by 2^11)
DINL void mma_f16(uint32_t d[2], const uint32_t a[4], const uint32_t b[2]) {
    asm volatile(
        "mma.sync.aligned.m16n8k16.row.col.f16.f16.f16.f16 "
        "{%0,%1}, {%2,%3,%4,%5}, {%6,%7}, {%0,%1};\n"
        : "+r"(d[0]), "+r"(d[1])
        : "r"(a[0]), "r"(a[1]), "r"(a[2]), "r"(a[3]), "r"(b[0]), "r"(b[1]));
}

// combined value: c32 + 2^-11 * c16[r]
DINL float cval(const float cc[4], const uint32_t ch[2], int r) {
    __half2 p = *reinterpret_cast<const __half2*>(&ch[r >> 1]);
    float corr = (r & 1) ? __high2float(p) : __low2float(p);
    return cc[r] + LO_INV * corr;
}

// chunk index f (0..511) -> (row, 16B-chunk); row permutation keeps STS.128
// 8-lane phases on rows (j, j+4): banks 0-15 / 16-31, fully conflict-free.
DINL void chunk_rc(int f, int& row, int& cc) {
    int q = f >> 2;
    cc = f & 3;
    row = (q & ~7) | ((q & 1) << 2) | ((q >> 1) & 3);
}

// ---------------- global fp16 tile -> staging regs (128 rows x 32 halfs) ----------------
template <int LD>
DINL void ldg_tileH(const __half* __restrict__ g, int kt, uint4 v[2], int tid) {
#pragma unroll
    for (int i = 0; i < 2; i++) {
        int r, cc;
        chunk_rc(tid + (i << 8), r, cc);
        v[i] = *reinterpret_cast<const uint4*>(g + (size_t)r * LD + kt * BK + (cc << 3));
    }
}

DINL void sts_tileH(uint32_t* smw, int buf, const uint4 v[2], int tid) {
#pragma unroll
    for (int i = 0; i < 2; i++) {
        int r, cc;
        chunk_rc(tid + (i << 8), r, cc);
        *reinterpret_cast<uint4*>(smw + buf * ABUF_W + r * WStr + (cc << 2)) = v[i];
    }
}

// ---------------- compute one 128x128x32 tile (R14-proven order) ----------------
DINL void compute_tile(const uint32_t* smAh, const uint32_t* smBh, const uint32_t* smBl,
                       int buf, float c[4][4][4], uint32_t ch[4][4][2]) {
    const int lane = threadIdx.x & 31, warp = threadIdx.x >> 5;
    const int wm = warp >> 2, wn = warp & 3, g = lane >> 2, tg = lane & 3;
    const int base = buf * ABUF_W;
#pragma unroll
    for (int kk = 0; kk < 2; kk++) {
        uint32_t bh[4][2], bl[4][2];
#pragma unroll
        for (int nf = 0; nf < 4; nf++) {
            int o = base + (wn * 32 + nf * 8 + g) * WStr + kk * 8 + tg;
            bh[nf][0] = smBh[o]; bh[nf][1] = smBh[o + 4];
            bl[nf][0] = smBl[o]; bl[nf][1] = smBl[o + 4];
        }
#pragma unroll
        for (int mf = 0; mf < 4; mf++) {
            int o = base + (wm * 64 + mf * 16 + g) * WStr + kk * 8 + tg;
            int o8 = o + 8 * WStr;
            uint32_t ah[4] = { smAh[o], smAh[o8], smAh[o + 4], smAh[o8 + 4] };
            // pass-grouped: accumulator RAW gap = 4 MMAs per pass
#pragma unroll
            for (int nf = 0; nf < 4; nf++) mma_f32(c[mf][nf], ah, bh[nf]);   // hi*hi
#pragma unroll
            for (int nf = 0; nf < 4; nf++) mma_f16(ch[mf][nf], ah, bl[nf]);  // hi*lo
        }
    }
}

// ---------------- full GEMM mainloop (double-buffered sync LDG/STS) ----------------
template <int KT, int LDA, int LDB>
DINL void gemm_main(const __half* __restrict__ Ag, const __half* __restrict__ Bhg,
                    const __half* __restrict__ Blg,
                    uint32_t* sm, float c[4][4][4], uint32_t ch[4][4][2]) {
    const int tid = threadIdx.x;
    uint32_t* Ah = sm;
    uint32_t* Bh = sm + 2 * ABUF_W;
    uint32_t* Bl = sm + 4 * ABUF_W;

#pragma unroll
    for (int mf = 0; mf < 4; mf++)
#pragma unroll
        for (int nf = 0; nf < 4; nf++) {
#pragma unroll
            for (int r = 0; r < 4; r++) c[mf][nf][r] = 0.0f;
            ch[mf][nf][0] = 0u;
            ch[mf][nf][1] = 0u;
        }

    uint4 va[2], vbh[2], vbl[2];
    ldg_tileH<LDA>(Ag, 0, va, tid);
    ldg_tileH<LDB>(Bhg, 0, vbh, tid);
    ldg_tileH<LDB>(Blg, 0, vbl, tid);
    sts_tileH(Ah, 0, va, tid);
    sts_tileH(Bh, 0, vbh, tid);
    sts_tileH(Bl, 0, vbl, tid);
    __syncthreads();

    for (int kt = 0; kt < KT; kt++) {
        int buf = kt & 1;
        if (kt + 1 < KT) {
            ldg_tileH<LDA>(Ag, kt + 1, va, tid);
            ldg_tileH<LDB>(Bhg, kt + 1, vbh, tid);
            ldg_tileH<LDB>(Blg, kt + 1, vbl, tid);
        }
        compute_tile(Ah, Bh, Bl, buf, c, ch);
        if (kt + 1 < KT) {
            sts_tileH(Ah, buf ^ 1, va, tid);
            sts_tileH(Bh, buf ^ 1, vbh, tid);
            sts_tileH(Bl, buf ^ 1, vbl, tid);
        }
        __syncthreads();
    }
}

// ---------------- kernel 1: fp32 -> fp16 conversions (x hi; W hi+lo) ----------------
constexpr int XN4 = (B_ * S_ * D_) / 4;   // 6291456
constexpr int WN4 = (D_ * D_) / 4;        // 147456
constexpr int XB  = XN4 / 256;            // 24576 blocks
constexpr int WB  = WN4 / 256;            // 576 blocks

__global__ void __launch_bounds__(256)
k_convall(const float* __restrict__ x, const float* __restrict__ Wq,
          const float* __restrict__ Wk, const float* __restrict__ Wv) {
    int bid = blockIdx.x;
    if (bid < XB) {
        int i = bid * 256 + threadIdx.x;
        float4 v = reinterpret_cast<const float4*>(x)[i];
        uint2 h;
        h.x = pack_h2(v.x, v.y);
        h.y = pack_h2(v.z, v.w);
        reinterpret_cast<uint2*>(g_xh)[i] = h;
    } else {
        int zz = (bid - XB) / WB;
        int i = ((bid - XB) % WB) * 256 + threadIdx.x;
        const float* W = (zz == 0) ? Wq : (zz == 1) ? Wk : Wv;
        float4 v = reinterpret_cast<const float4*>(W)[i];
        uint2 h, l;
        h.x = pack_h2(v.x, v.y);
        h.y = pack_h2(v.z, v.w);
        l.x = lo_h2(v.x, v.y, h.x);
        l.y = lo_h2(v.z, v.w, h.y);
        size_t off = (size_t)zz * (D_ * D_ / 4) + i;
        reinterpret_cast<uint2*>(g_Wh)[off] = h;
        reinterpret_cast<uint2*>(g_Wl)[off] = l;
    }
}

// ---------------- kernel 2: RoPE cos/sin tables ----------------
__global__ void k_ropetab() {
    int idx = blockIdx.x * 256 + threadIdx.x;
    if (idx >= S_ * HALF) return;
    int s = idx / HALF, i = idx - s * HALF;
    float e = (2.0f * (float)i) / 768.0f;
    float invf = 1.0f / powf(10000.0f, e);
    float ang = (float)s * invf;
    float sn, cs;
    sincosf(ang, &sn, &cs);
    g_cosT[idx] = cs;
    g_sinT[idx] = sn;
}

// ---------------- kernel 3: QKV projection + bias + RoPE -> fp16 outputs ----------------
__global__ void __launch_bounds__(NT, 1)
k_qkv(const float* __restrict__ bq, const float* __restrict__ bk, const float* __restrict__ bv) {
    extern __shared__ uint32_t sm[];
    int z = blockIdx.z;
    const float* bb = (z == 0) ? bq : (z == 1) ? bk : bv;
    const int bm = blockIdx.y * BM, bn = blockIdx.x * BN;

    float c[4][4][4];
    uint32_t ch[4][4][2];
    gemm_main<24, D_, D_>(g_xh + (size_t)bm * D_,
                          g_Wh + (size_t)z * D_ * D_ + (size_t)bn * D_,
                          g_Wl + (size_t)z * D_ * D_ + (size_t)bn * D_, sm, c, ch);

    const int lane = threadIdx.x & 31, warp = threadIdx.x >> 5;
    const int wm = warp >> 2, wn = warp & 3, g = lane >> 2, tg = lane & 3;
    const float qscale = 0.03608439182435161f;  // 1/sqrt(768)
#pragma unroll
    for (int mf = 0; mf < 4; mf++) {
#pragma unroll
        for (int h = 0; h < 2; h++) {
            int r = bm + wm * 64 + mf * 16 + g + h * 8;
            int s = r & (S_ - 1);
            int b = r >> 10;
#pragma unroll
            for (int nf = 0; nf < 4; nf++) {
                int col = bn + wn * 32 + nf * 8 + 2 * tg;
                float2 bia = *reinterpret_cast<const float2*>(bb + col);
                float v0 = cval(c[mf][nf], ch[mf][nf], h * 2 + 0) + bia.x;
                float v1 = cval(c[mf][nf], ch[mf][nf], h * 2 + 1) + bia.y;
                if (z < 2) {
                    int i = col >> 1;
                    float cs = g_cosT[s * HALF + i];
                    float sn = g_sinT[s * HALF + i];
                    float t0 = v0 * cs - v1 * sn;
                    v1 = v0 * sn + v1 * cs;
                    v0 = t0;
                    size_t off = (size_t)r * D_ + col;
                    if (z == 0) {
                        v0 *= qscale; v1 *= qscale;
                        *reinterpret_cast<uint32_t*>(g_Qh + off) = pack_h2(v0, v1);
                    } else {
                        uint32_t hp = pack_h2(v0, v1);
                        *reinterpret_cast<uint32_t*>(g_Kh + off) = hp;
                        *reinterpret_cast<uint32_t*>(g_Kl + off) = lo_h2(v0, v1, hp);
                    }
                } else {
                    size_t boff = (size_t)b * D_ * S_;
                    __half h0 = __float2half_rn(v0);
                    __half h1 = __float2half_rn(v1);
                    g_Vth[boff + (size_t)col * S_ + s]       = h0;
                    g_Vth[boff + (size_t)(col + 1) * S_ + s] = h1;
                    g_Vtl[boff + (size_t)col * S_ + s] =
                        __float2half_rn((v0 - __half2float(h0)) * LO_SCALE);
                    g_Vtl[boff + (size_t)(col + 1) * S_ + s] =
                        __float2half_rn((v1 - __half2float(h1)) * LO_SCALE);
                }
            }
        }
    }
}

// ---------------- kernel 4: scores = (Q*scale) K^T -> fp32 ----------------
__global__ void __launch_bounds__(NT, 1)
k_scores() {
    extern __shared__ uint32_t sm[];
    int z = blockIdx.z;
    const int bm = blockIdx.y * BM, bn = blockIdx.x * BN;
    size_t ao = (size_t)z * S_ * D_ + (size_t)bm * D_;
    size_t bo = (size_t)z * S_ * D_ + (size_t)bn * D_;
    float* C = g_S + (size_t)z * S_ * S_;

    float c[4][4][4];
    uint32_t ch[4][4][2];
    gemm_main<24, D_, D_>(g_Qh + ao, g_Kh + bo, g_Kl + bo, sm, c, ch);

    const int lane = threadIdx.x & 31, warp = threadIdx.x >> 5;
    const int wm = warp >> 2, wn = warp & 3, g = lane >> 2, tg = lane & 3;
#pragma unroll
    for (int mf = 0; mf < 4; mf++) {
#pragma unroll
        for (int h = 0; h < 2; h++) {
            int r = bm + wm * 64 + mf * 16 + g + h * 8;
#pragma unroll
            for (int nf = 0; nf < 4; nf++) {
                int col = bn + wn * 32 + nf * 8 + 2 * tg;
                *reinterpret_cast<float2*>(C + (size_t)r * S_ + col) =
                    make_float2(cval(c[mf][nf], ch[mf][nf], h * 2 + 0),
                                cval(c[mf][nf], ch[mf][nf], h * 2 + 1));
            }
        }
    }
}

// ---------------- kernel 5: row softmax -> fp16 P (hi) ----------------
__global__ void __launch_bounds__(128)
k_softmax() {
    const float* p = g_S + (size_t)blockIdx.x * S_;
    int t = threadIdx.x;
    float4 a = reinterpret_cast<const float4*>(p)[t];
    float4 b = reinterpret_cast<const float4*>(p)[t + 128];

    float m = fmaxf(fmaxf(fmaxf(a.x, a.y), fmaxf(a.z, a.w)),
                    fmaxf(fmaxf(b.x, b.y), fmaxf(b.z, b.w)));
#pragma unroll
    for (int o = 16; o > 0; o >>= 1) m = fmaxf(m, __shfl_xor_sync(0xffffffffu, m, o));
    __shared__ float r1[4], r2[4];
    if ((t & 31) == 0) r1[t >> 5] = m;
    __syncthreads();
    m = fmaxf(fmaxf(r1[0], r1[1]), fmaxf(r1[2], r1[3]));

    a.x = expf(a.x - m); a.y = expf(a.y - m); a.z = expf(a.z - m); a.w = expf(a.w - m);
    b.x = expf(b.x - m); b.y = expf(b.y - m); b.z = expf(b.z - m); b.w = expf(b.w - m);
    float s = a.x + a.y + a.z + a.w + b.x + b.y + b.z + b.w;
#pragma unroll
    for (int o = 16; o > 0; o >>= 1) s += __shfl_xor_sync(0xffffffffu, s, o);
    if ((t & 31) == 0) r2[t >> 5] = s;
    __syncthreads();
    s = r2[0] + r2[1] + r2[2] + r2[3];
    float inv = 1.0f / s;
    a.x *= inv; a.y *= inv; a.z *= inv; a.w *= inv;
    b.x *= inv; b.y *= inv; b.z *= inv; b.w *= inv;

    uint32_t* ph = reinterpret_cast<uint32_t*>(g_Ph + (size_t)blockIdx.x * S_);
    ph[2 * t]       = pack_h2(a.x, a.y);
    ph[2 * t + 1]   = pack_h2(a.z, a.w);
    ph[2 * t + 256] = pack_h2(b.x, b.y);
    ph[2 * t + 257] = pack_h2(b.z, b.w);
}

// ---------------- kernel 6: out = P V (NT via transposed V) ----------------
__global__ void __launch_bounds__(NT, 1)
k_pv(float* __restrict__ out) {
    extern __shared__ uint32_t sm[];
    int z = blockIdx.z;
    const int bm = blockIdx.y * BM, bn = blockIdx.x * BN;
    size_t ao = (size_t)z * S_ * S_ + (size_t)bm * S_;
    size_t bo = (size_t)z * D_ * S_ + (size_t)bn * S_;
    float* C = out + (size_t)z * S_ * D_;

    float c[4][4][4];
    uint32_t ch[4][4][2];
    gemm_main<32, S_, S_>(g_Ph + ao, g_Vth + bo, g_Vtl + bo, sm, c, ch);

    const int lane = threadIdx.x & 31, warp = threadIdx.x >> 5;
    const int wm = warp >> 2, wn = warp & 3, g = lane >> 2, tg = lane & 3;
#pragma unroll
    for (int mf = 0; mf < 4; mf++) {
#pragma unroll
        for (int h = 0; h < 2; h++) {
            int r = bm + wm * 64 + mf * 16 + g + h * 8;
#pragma unroll
            for (int nf = 0; nf < 4; nf++) {
                int col = bn + wn * 32 + nf * 8 + 2 * tg;
                *reinterpret_cast<float2*>(C + (size_t)r * D_ + col) =
                    make_float2(cval(c[mf][nf], ch[mf][nf], h * 2 + 0),
                                cval(c[mf][nf], ch[mf][nf], h * 2 + 1));
            }
        }
    }
}

// ---------------- launch ----------------
extern "C" void kernel_launch(void* const* d_in, const int* in_sizes, int n_in,
                              void* d_out, int out_size) {
    const float* x  = (const float*)d_in[0];
    const float* Wq = (const float*)d_in[1];
    const float* bq = (const float*)d_in[2];
    const float* Wk = (const float*)d_in[3];
    const float* bk = (const float*)d_in[4];
    const float* Wv = (const float*)d_in[5];
    const float* bv = (const float*)d_in[6];
    float* out = (float*)d_out;

    cudaFuncSetAttribute(k_qkv,    cudaFuncAttributeMaxDynamicSharedMemorySize, SMEM_SZ);
    cudaFuncSetAttribute(k_scores, cudaFuncAttributeMaxDynamicSharedMemorySize, SMEM_SZ);
    cudaFuncSetAttribute(k_pv,     cudaFuncAttributeMaxDynamicSharedMemorySize, SMEM_SZ);

    // launches: convall(1), ropetab(2), qkv(3), scores(4 = ncu capture slot)
    k_convall<<<XB + 3 * WB, 256>>>(x, Wq, Wk, Wv);
    k_ropetab<<<(S_ * HALF + 255) / 256, 256>>>();
    k_qkv<<<dim3(D_ / BN, (B_ * S_) / BM, 3), NT, SMEM_SZ>>>(bq, bk, bv);
    k_scores<<<dim3(S_ / BN, S_ / BM, B_), NT, SMEM_SZ>>>();
    k_softmax<<<dim3(B_ * S_), 128>>>();
    k_pv<<<dim3(D_ / BN, S_ / BM, B_), NT, SMEM_SZ>>>(out);
}